// round 6
// baseline (speedup 1.0000x reference)
#include <cuda_runtime.h>
#include <math.h>

// RNN-T greedy decode, persistent-kernel fp32 + cp.async staged weights.
#define B 8
#define T 200
#define H 1024
#define NV 16385
#define BLANK 16384
#define MAXSYM 4
#define NSTEP (T * MAXSYM) // 800
#define G 148
#define NTHR 512
#define JTILE 112          // vocab cols per block in joint (148*112 = 16576 >= NV)

// ---------------- device scratch ----------------
__device__ __align__(16) float g_encT[T * B * H];
__device__ __align__(16) float g_E[T * B * H];
__device__ __align__(16) float g_WoutT[(size_t)G * 1024 * JTILE + 256];
__device__ __align__(16) float g_Wl[(size_t)128 * 1024 * 64 + 128];
__device__ __align__(16) float g_WpT[H * H];
__device__ float g_h[B * H];
__device__ float g_c[B * H];
__device__ float g_h2[2][B * H];
__device__ float g_c2[2][B * H];
__device__ float g_qkb[H * B];
__device__ int   g_lastbuf[2][B];
__device__ int   g_advbuf[2][B];
__device__ unsigned long long g_amax[2][B];
__device__ unsigned g_leaf[8];
__device__ unsigned g_root;
__device__ unsigned g_gen;

// ---------------- helpers ----------------
__device__ __forceinline__ unsigned long long ffma2(unsigned long long a,
                                                    unsigned long long b,
                                                    unsigned long long c) {
    unsigned long long d;
    asm("fma.rn.f32x2 %0, %1, %2, %3;" : "=l"(d) : "l"(a), "l"(b), "l"(c));
    return d;
}
__device__ __forceinline__ unsigned long long dup2(float w) {
    unsigned long long r;
    unsigned u = __float_as_uint(w);
    asm("mov.b64 %0, {%1, %1};" : "=l"(r) : "r"(u));
    return r;
}
__device__ __forceinline__ void unpack2(unsigned long long v, float& lo, float& hi) {
    unsigned a, b;
    asm("mov.b64 {%0, %1}, %2;" : "=r"(a), "=r"(b) : "l"(v));
    lo = __uint_as_float(a); hi = __uint_as_float(b);
}
__device__ __forceinline__ unsigned long long pack_key(float f, int v) {
    unsigned u = __float_as_uint(f);
    u = (u & 0x80000000u) ? ~u : (u | 0x80000000u);
    return ((unsigned long long)u << 32) | (unsigned)(BLANK - v);
}
__device__ __forceinline__ float sigm(float x) { return 1.0f / (1.0f + expf(-x)); }

__device__ __forceinline__ void cp16(unsigned dst, const float* src) {
    asm volatile("cp.async.cg.shared.global [%0], [%1], 16;" :: "r"(dst), "l"(src));
}
__device__ __forceinline__ void cp_commit() { asm volatile("cp.async.commit_group;"); }
__device__ __forceinline__ void cp_wait1()  { asm volatile("cp.async.wait_group 1;"); }
__device__ __forceinline__ void cp_wait0()  { asm volatile("cp.async.wait_group 0;"); }

// two-level barrier: 8 leaf counters + root, cumulative (no resets)
__device__ __forceinline__ void grid_sync(int bid) {
    __syncthreads();
    if (threadIdx.x == 0) {
        __threadfence();
        unsigned gen = *(volatile unsigned*)&g_gen;
        int leaf = bid & 7;
        unsigned cnt = (leaf < 4) ? 19u : 18u;   // 4*19 + 4*18 = 148
        unsigned t = atomicAdd(&g_leaf[leaf], 1u);
        if ((t % cnt) == cnt - 1u) {
            unsigned rt = atomicAdd(&g_root, 1u);
            if ((rt & 7u) == 7u) {
                __threadfence();
                atomicExch(&g_gen, gen + 1u);
            }
        }
        while (*(volatile unsigned*)&g_gen == gen) {}
        __threadfence();
    }
    __syncthreads();
}

// ---------------- setup kernels ----------------
__global__ void k_setup1(const float* __restrict__ enc, const float* __restrict__ W_pred) {
    __shared__ float tile[32][33];
    int bidx = blockIdx.x;
    int tx = threadIdx.x, ty = threadIdx.y;   // 32 x 8
    if (bidx < 1792) {
        int b = bidx & 7, kb = ((bidx >> 3) & 31) * 32, tb = (bidx >> 8) * 32;
#pragma unroll
        for (int i = 0; i < 4; i++) {
            int k = kb + ty + i * 8, t = tb + tx;
            tile[ty + i * 8][tx] = (t < T) ? enc[(size_t)b * H * T + (size_t)k * T + t] : 0.0f;
        }
        __syncthreads();
#pragma unroll
        for (int i = 0; i < 4; i++) {
            int t = tb + ty + i * 8, k = kb + tx;
            if (t < T) g_encT[((size_t)t * B + b) * H + k] = tile[tx][ty + i * 8];
        }
        if (bidx == 0) {
            int tid = ty * 32 + tx;
            for (int i = tid; i < B * H; i += 256) { g_h[i] = 0.0f; g_c[i] = 0.0f; }
            if (tid < B) { g_amax[0][tid] = 0ull; g_amax[1][tid] = 0ull; }
        }
    } else {
        int j = bidx - 1792;
        int kb = (j & 31) * 32, jb = (j >> 5) * 32;
#pragma unroll
        for (int i = 0; i < 4; i++)
            tile[ty + i * 8][tx] = W_pred[(size_t)(kb + ty + i * 8) * H + jb + tx];
        __syncthreads();
#pragma unroll
        for (int i = 0; i < 4; i++)
            g_WpT[(size_t)(jb + ty + i * 8) * H + kb + tx] = tile[tx][ty + i * 8];
    }
}

__global__ void k_setup2(const float* __restrict__ W_out, const float* __restrict__ Wx,
                         const float* __restrict__ Wh) {
    int bid = blockIdx.x;
    int tid = threadIdx.x;   // 128
    if (bid < G * 1024) {
        int tileI = bid >> 10, k = bid & 1023;
        if (tid < JTILE) {
            int v = tileI * JTILE + tid;
            g_WoutT[((size_t)tileI * 1024 + k) * JTILE + tid] =
                (v < NV) ? W_out[(size_t)k * NV + v] : 0.0f;
        }
    } else {
        int j = bid - G * 1024;
        int tileI = j >> 10, k = j & 1023;
        if (tid < 64) {
            float val;
            if (tid < 32) val = Wx[(size_t)k * 4096 + (tid >> 3) * 1024 + tileI * 8 + (tid & 7)];
            else { int l2 = tid - 32; val = Wh[(size_t)k * 4096 + (l2 >> 3) * 1024 + tileI * 8 + (l2 & 7)]; }
            g_Wl[((size_t)tileI * 1024 + k) * 64 + tid] = val;
        }
    }
}

__global__ void k_egemm(const float* __restrict__ W_enc, const float* __restrict__ b_joint) {
    __shared__ float xs[B * H];
    int t = blockIdx.y;
    int j = blockIdx.x * 256 + threadIdx.x;
    for (int idx = threadIdx.x; idx < B * H; idx += 256)
        xs[idx] = g_encT[(size_t)t * B * H + idx];
    __syncthreads();
    float acc[B];
#pragma unroll
    for (int b = 0; b < B; b++) acc[b] = 0.0f;
    for (int k = 0; k < H; k += 4) {
        float w0 = __ldg(&W_enc[(size_t)(k + 0) * H + j]);
        float w1 = __ldg(&W_enc[(size_t)(k + 1) * H + j]);
        float w2 = __ldg(&W_enc[(size_t)(k + 2) * H + j]);
        float w3 = __ldg(&W_enc[(size_t)(k + 3) * H + j]);
#pragma unroll
        for (int b = 0; b < B; b++) {
            float4 q4 = *(const float4*)&xs[b * H + k];
            acc[b] = fmaf(q4.x, w0, acc[b]);
            acc[b] = fmaf(q4.y, w1, acc[b]);
            acc[b] = fmaf(q4.z, w2, acc[b]);
            acc[b] = fmaf(q4.w, w3, acc[b]);
        }
    }
    float bj = __ldg(&b_joint[j]);
#pragma unroll
    for (int b = 0; b < B; b++)
        g_E[((size_t)t * B + b) * H + j] = acc[b] + bj;
}

// ---------------- persistent decode kernel ----------------
// smem layout (floats):
//  LSTM : xs[0..8192) hs[8192..16384) wbufs[16384..32768) ; redu aliased @16384 (16384) ; zs @32768
//  pred : h2kb[0..8192) prsh @8192
//  joint: qs[0..8192) wbufs[8192..36864) ; redu aliased @8192 ; keyb @24576 ; spart @26368
#define SMEM_FLOATS 36864

__global__ void __launch_bounds__(NTHR, 1)
k_decode(const float* __restrict__ emb, const float* __restrict__ bias,
         const float* __restrict__ b_out,
         const int* __restrict__ lens, float* __restrict__ out) {
    extern __shared__ float sm[];
    __shared__ int s_adv[8];
    __shared__ int s_last[8];
    int tid = threadIdx.x, bid = blockIdx.x;
    unsigned smb = (unsigned)__cvta_generic_to_shared(sm);

    for (int s = 0; s < NSTEP; s++) {
        int p = s & 1;
        int is_start = (s == 0);

        // ---- decisions for step s-1 ----
        if (tid < 8) {
            int b = tid, advance = 0, lastv = BLANK;
            if (s > 0) {
                int d = s - 1, dp = d & 1;
                unsigned long long key = g_amax[dp][b];
                int sym = BLANK - (int)(unsigned)(key & 0xffffffffu);
                int t = d >> 2, u = d & 3;
                int active = (u == 0) ? (t < lens[b]) : g_advbuf[dp ^ 1][b];
                advance = (active && sym != BLANK) ? 1 : 0;
                int prev_last = (d == 0) ? BLANK : g_lastbuf[dp ^ 1][b];
                lastv = advance ? sym : prev_last;
                g_advbuf[dp][b] = advance;
                g_lastbuf[dp][b] = lastv;
                if (bid == 0)
                    out[(size_t)b * NSTEP + t * MAXSYM + u] = (float)(active ? sym : BLANK);
            }
            s_adv[tid] = advance;
            s_last[tid] = lastv;
        }
        if (bid == 0 && tid >= 32 && tid < 40) g_amax[p][tid - 32] = 0ull;
        __syncthreads();

        // ---- LSTM (blocks 0..127) ----
        if (bid < 128) {
            const float* h2prev = g_h2[p ^ 1];
            float* xs = sm;
            float* hs = sm + 8192;
#pragma unroll
            for (int bb = 0; bb < 8; bb++) {
                int adv = s_adv[bb];
                const float* hsrc = adv ? (h2prev + bb * H) : (g_h + bb * H);
                const float* xsrc = emb + (size_t)s_last[bb] * H;
                for (int k = tid; k < H; k += NTHR) {
                    float hv = 0.0f, xv = 0.0f;
                    if (!is_start) { hv = hsrc[k]; xv = __ldg(&xsrc[k]); }
                    hs[k * 8 + bb] = hv;
                    xs[k * 8 + bb] = xv;
                }
            }
            __syncthreads();
            if (tid < 64) {   // commit h
                int idx = bid * 64 + tid;
                int b = idx >> 10, k = idx & 1023;
                g_h[idx] = hs[k * 8 + b];
            }

            {
                int w = tid >> 5, lane = tid & 31;
                int rsub = lane >> 3, jg = lane & 7;
                const float* wtile = g_Wl + ((size_t)bid * 1024 + 64 * w) * 64;
                unsigned bufb = smb + (16384 + w * 1024) * 4;
                const unsigned long long* xu = (const unsigned long long*)xs;
                const unsigned long long* hu = (const unsigned long long*)hs;
                unsigned long long acc[4][4];
#pragma unroll
                for (int c = 0; c < 4; c++)
#pragma unroll
                    for (int bp = 0; bp < 4; bp++) acc[c][bp] = 0ull;

                // prologue: stage chunks 0,1
#pragma unroll
                for (int pc = 0; pc < 2; pc++) {
                    const float* src = wtile + (size_t)(8 * pc) * 64;
                    unsigned dst = bufb + pc * 512 * 4;
#pragma unroll
                    for (int i = 0; i < 4; i++)
                        cp16(dst + (lane + 32 * i) * 16, src + (lane + 32 * i) * 4);
                    cp_commit();
                }
#pragma unroll
                for (int ch = 0; ch < 8; ch++) {
                    if (ch == 7) cp_wait0(); else cp_wait1();
                    __syncwarp();
                    int fb = 16384 + w * 1024 + (ch & 1) * 512;
#pragma unroll
                    for (int r = 0; r < 2; r++) {
                        int rr = rsub + 4 * r;
                        int k = 64 * w + 8 * ch + rr;
                        float4 wx4 = *(const float4*)&sm[fb + rr * 64 + jg * 4];
                        float4 wh4 = *(const float4*)&sm[fb + rr * 64 + 32 + jg * 4];
                        unsigned long long wx2[4] = {dup2(wx4.x), dup2(wx4.y), dup2(wx4.z), dup2(wx4.w)};
                        unsigned long long wh2[4] = {dup2(wh4.x), dup2(wh4.y), dup2(wh4.z), dup2(wh4.w)};
#pragma unroll
                        for (int bp = 0; bp < 4; bp++) {
                            unsigned long long xp = xu[k * 4 + bp];
                            unsigned long long hp = hu[k * 4 + bp];
#pragma unroll
                            for (int c = 0; c < 4; c++) {
                                acc[c][bp] = ffma2(xp, wx2[c], acc[c][bp]);
                                acc[c][bp] = ffma2(hp, wh2[c], acc[c][bp]);
                            }
                        }
                    }
                    __syncwarp();
                    if (ch < 6) {
                        const float* src = wtile + (size_t)(8 * (ch + 2)) * 64;
                        unsigned dst = bufb + (ch & 1) * 512 * 4;
#pragma unroll
                        for (int i = 0; i < 4; i++)
                            cp16(dst + (lane + 32 * i) * 16, src + (lane + 32 * i) * 4);
                        cp_commit();
                    }
                }
                __syncthreads();   // all compute done -> buffers dead, alias redu
                unsigned long long* redu = (unsigned long long*)(sm + 16384);
#pragma unroll
                for (int c = 0; c < 4; c++)
#pragma unroll
                    for (int bp = 0; bp < 4; bp++)
                        redu[(c * 4 + bp) * NTHR + tid] = acc[c][bp];
            }
            __syncthreads();
            if (tid < 256) {   // reduce: 32 cols x 8 b  (thread tid = kp*8+jg partials)
                int colIdx = tid >> 3, b = tid & 7;
                int jg = colIdx >> 2, c = colIdx & 3;
                int bp = b >> 1, lane = b & 1;
                const float* redf = sm + 16384;
                float z = 0.0f;
#pragma unroll 8
                for (int kp = 0; kp < 64; kp++)
                    z += redf[((c * 4 + bp) * NTHR + kp * 8 + jg) * 2 + lane];
                int gate = jg >> 1;
                int cc = (jg & 1) * 4 + c;
                z += __ldg(&bias[gate * 1024 + bid * 8 + cc]);
                float* zs = sm + 32768;
                zs[(gate * 8 + cc) * 8 + b] = z;
            }
            __syncthreads();
            if (tid < 64) {
                int b = tid & 7, ch = tid >> 3;
                int jh = bid * 8 + ch;
                const float* zs = sm + 32768;
                float zi = zs[(0 * 8 + ch) * 8 + b];
                float zf = zs[(1 * 8 + ch) * 8 + b];
                float zg = zs[(2 * 8 + ch) * 8 + b];
                float zo = zs[(3 * 8 + ch) * 8 + b];
                float c_eff = 0.0f;
                if (!is_start) c_eff = s_adv[b] ? g_c2[p ^ 1][b * H + jh] : g_c[b * H + jh];
                g_c[b * H + jh] = c_eff;
                float cn = sigm(zf) * c_eff + sigm(zi) * tanhf(zg);
                float hn = sigm(zo) * tanhf(cn);
                g_c2[p][b * H + jh] = cn;
                g_h2[p][b * H + jh] = hn;
            }
        }
        grid_sync(bid);

        // ---- pred: q = tanh(E[t] + h2 @ W_pred) (blocks 0..127) ----
        if (bid < 128) {
            const float* h2c = g_h2[p];
#pragma unroll
            for (int bb = 0; bb < 8; bb++)
                for (int k = tid; k < H; k += NTHR)
                    sm[k * 8 + bb] = h2c[bb * H + k];
            __syncthreads();
            int w = tid >> 5, lane = tid & 31;
            int jloc = w & 7, half = w >> 3;
            int j = bid * 8 + jloc;
            const float4* wp = (const float4*)(g_WpT + (size_t)j * H + half * 512);
            const unsigned long long* hu = (const unsigned long long*)sm;
            unsigned long long acc[4];
#pragma unroll
            for (int bp = 0; bp < 4; bp++) acc[bp] = 0ull;
#pragma unroll
            for (int cIt = 0; cIt < 4; cIt++) {
                int k = half * 512 + cIt * 128 + lane * 4;
                float4 w4 = wp[cIt * 32 + lane];
                unsigned long long w0 = dup2(w4.x), w1 = dup2(w4.y);
                unsigned long long w2 = dup2(w4.z), w3 = dup2(w4.w);
#pragma unroll
                for (int bp = 0; bp < 4; bp++) {
                    acc[bp] = ffma2(hu[(k + 0) * 4 + bp], w0, acc[bp]);
                    acc[bp] = ffma2(hu[(k + 1) * 4 + bp], w1, acc[bp]);
                    acc[bp] = ffma2(hu[(k + 2) * 4 + bp], w2, acc[bp]);
                    acc[bp] = ffma2(hu[(k + 3) * 4 + bp], w3, acc[bp]);
                }
            }
            float a[8];
#pragma unroll
            for (int bp = 0; bp < 4; bp++) unpack2(acc[bp], a[bp * 2], a[bp * 2 + 1]);
#pragma unroll
            for (int off = 16; off > 0; off >>= 1)
#pragma unroll
                for (int b = 0; b < 8; b++)
                    a[b] += __shfl_down_sync(0xffffffffu, a[b], off);
            float* prsh = sm + 8192;
            if (lane == 0) {
#pragma unroll
                for (int b = 0; b < 8; b++)
                    prsh[half * 64 + jloc * 8 + b] = a[b];
            }
            __syncthreads();
            if (tid < 64) {
                int jl = tid >> 3, b = tid & 7;
                int jj = bid * 8 + jl;
                int t = s >> 2;
                float v = prsh[jl * 8 + b] + prsh[64 + jl * 8 + b]
                        + g_E[((size_t)t * B + b) * H + jj];
                g_qkb[jj * 8 + b] = tanhf(v);
            }
        }
        grid_sync(bid);

        // ---- joint: logits = q @ W_out + b_out, argmax (all 148 blocks, 112 cols) ----
        {
            float* qs = sm;
            for (int i = tid; i < H * B; i += NTHR) qs[i] = g_qkb[i];
            __syncthreads();
            const unsigned long long* qu = (const unsigned long long*)qs;
            int w = tid >> 5, vg = tid & 31;
            int vgc = (vg < 28) ? vg : 27;
            const float* wtile = g_WoutT + ((size_t)bid * 1024 + 64 * w) * JTILE;
            unsigned bufb = smb + (8192 + w * 1792) * 4;
            unsigned long long acc[4][4];
#pragma unroll
            for (int c = 0; c < 4; c++)
#pragma unroll
                for (int bp = 0; bp < 4; bp++) acc[c][bp] = 0ull;

            // prologue: stage chunks 0,1
#pragma unroll
            for (int pc = 0; pc < 2; pc++) {
                const float* src = wtile + (size_t)(8 * pc) * JTILE;
                unsigned dst = bufb + pc * 896 * 4;
#pragma unroll
                for (int i = 0; i < 7; i++)
                    cp16(dst + (vg + 32 * i) * 16, src + (vg + 32 * i) * 4);
                cp_commit();
            }
#pragma unroll
            for (int ch = 0; ch < 8; ch++) {
                if (ch == 7) cp_wait0(); else cp_wait1();
                __syncwarp();
                int fb = 8192 + w * 1792 + (ch & 1) * 896;
#pragma unroll
                for (int rr = 0; rr < 8; rr++) {
                    int k = 64 * w + 8 * ch + rr;
                    float4 wv = *(const float4*)&sm[fb + rr * JTILE + vgc * 4];
                    unsigned long long w0 = dup2(wv.x), w1 = dup2(wv.y);
                    unsigned long long w2 = dup2(wv.z), w3 = dup2(wv.w);
#pragma unroll
                    for (int bp = 0; bp < 4; bp++) {
                        unsigned long long qp = qu[k * 4 + bp];
                        acc[0][bp] = ffma2(qp, w0, acc[0][bp]);
                        acc[1][bp] = ffma2(qp, w1, acc[1][bp]);
                        acc[2][bp] = ffma2(qp, w2, acc[2][bp]);
                        acc[3][bp] = ffma2(qp, w3, acc[3][bp]);
                    }
                }
                __syncwarp();
                if (ch < 6) {
                    const float* src = wtile + (size_t)(8 * (ch + 2)) * JTILE;
                    unsigned dst = bufb + (ch & 1) * 896 * 4;
#pragma unroll
                    for (int i = 0; i < 7; i++)
                        cp16(dst + (vg + 32 * i) * 16, src + (vg + 32 * i) * 4);
                    cp_commit();
                }
            }
            __syncthreads();   // all compute done -> buffers dead, alias redu
            unsigned long long* redu = (unsigned long long*)(sm + 8192);
            const float* redf = sm + 8192;
#pragma unroll
            for (int c = 0; c < 4; c++)
#pragma unroll
                for (int bp = 0; bp < 4; bp++)
                    redu[(c * 4 + bp) * NTHR + tid] = acc[c][bp];
            __syncthreads();
            // reduce + keys: 896 outputs (112 cols x 8 b)
            unsigned long long* keyb = (unsigned long long*)(sm + 24576);
            for (int o = tid; o < JTILE * 8; o += NTHR) {
                int b = o / JTILE, col = o - b * JTILE;
                int vg2 = col >> 2, c = col & 3, bp = b >> 1, lane = b & 1;
                float sv = 0.0f;
#pragma unroll
                for (int kc2 = 0; kc2 < 16; kc2++)
                    sv += redf[((c * 4 + bp) * NTHR + kc2 * 32 + vg2) * 2 + lane];
                int v = bid * JTILE + col;
                unsigned long long key = 0ull;
                if (v < NV) key = pack_key(sv + __ldg(&b_out[v]), v);
                keyb[o] = key;
            }
            __syncthreads();
            unsigned long long* spart = (unsigned long long*)(sm + 26368);
            if (tid < 64) {
                int b = tid >> 3, part = tid & 7;
                unsigned long long m = 0ull;
#pragma unroll
                for (int cc = 0; cc < 14; cc++) {
                    unsigned long long kk = keyb[b * JTILE + part * 14 + cc];
                    if (kk > m) m = kk;
                }
                spart[tid] = m;
            }
            __syncthreads();
            if (tid < 8) {
                unsigned long long m = 0ull;
#pragma unroll
                for (int pp = 0; pp < 8; pp++) {
                    unsigned long long kk = spart[tid * 8 + pp];
                    if (kk > m) m = kk;
                }
                atomicMax(&g_amax[p][tid], m);
            }
        }
        grid_sync(bid);
    }

    // ---- final decision + h,c output ----
    {
        int d = NSTEP - 1, dp = d & 1;
        if (tid < 8) {
            int b = tid;
            unsigned long long key = g_amax[dp][b];
            int sym = BLANK - (int)(unsigned)(key & 0xffffffffu);
            int t = d >> 2, u = d & 3;
            int active = (u == 0) ? (t < lens[b]) : g_advbuf[dp ^ 1][b];
            int advance = (active && sym != BLANK) ? 1 : 0;
            if (bid == 0)
                out[(size_t)b * NSTEP + t * MAXSYM + u] = (float)(active ? sym : BLANK);
            s_adv[tid] = advance;
        }
        __syncthreads();
        for (int i = bid * NTHR + tid; i < B * H; i += G * NTHR) {
            int b = i >> 10;
            float hf = s_adv[b] ? g_h2[dp][i] : g_h[i];
            float cf = s_adv[b] ? g_c2[dp][i] : g_c[i];
            out[B * NSTEP + i] = hf;
            out[B * NSTEP + B * H + i] = cf;
        }
    }
}

extern "C" void kernel_launch(void* const* d_in, const int* in_sizes, int n_in,
                              void* d_out, int out_size) {
    (void)in_sizes; (void)n_in; (void)out_size;
    const float* enc     = (const float*)d_in[0];
    const int*   lens    = (const int*)d_in[1];
    const float* emb     = (const float*)d_in[2];
    const float* Wx      = (const float*)d_in[3];
    const float* Wh      = (const float*)d_in[4];
    const float* bias    = (const float*)d_in[5];
    const float* W_enc   = (const float*)d_in[6];
    const float* W_pred  = (const float*)d_in[7];
    const float* b_joint = (const float*)d_in[8];
    const float* W_out   = (const float*)d_in[9];
    const float* b_out   = (const float*)d_in[10];
    float* out = (float*)d_out;

    static int configured = 0;
    if (!configured) {
        cudaFuncSetAttribute(k_decode, cudaFuncAttributeMaxDynamicSharedMemorySize,
                             SMEM_FLOATS * 4);
        configured = 1;
    }

    k_setup1<<<2816, dim3(32, 8)>>>(enc, W_pred);
    k_setup2<<<G * 1024 + 128 * 1024, 128>>>(W_out, Wx, Wh);
    k_egemm<<<dim3(4, T), 256>>>(W_enc, b_joint);
    k_decode<<<G, NTHR, SMEM_FLOATS * 4>>>(emb, bias, b_out, lens, out);
}